// round 10
// baseline (speedup 1.0000x reference)
#include <cuda_runtime.h>
#include <float.h>

#define VX 64
#define NB 8
#define NP 32
#define PE 32
#define SHARP 100.0f
#define EPSF 1e-8f
#define NTHREADS 512
#define NWARPS 16

__device__ __forceinline__ float ex2_approx(float x) {
    float r; asm("ex2.approx.ftz.f32 %0, %1;" : "=f"(r) : "f"(x)); return r;
}
__device__ __forceinline__ float rcp_approx(float x) {
    float r; asm("rcp.approx.ftz.f32 %0, %1;" : "=f"(r) : "f"(x)); return r;
}

// Block: one (batch b, row y), 16 warps, 2 pixels per lane.
// Valid polys compacted and dealt round-robin to 16 warps (critical warp does
// ceil(nv/16) polys). Parity is precomputed per polygon as a 64-bit pixel mask
// in Phase 1 (crossing threshold is monotone in px), so the 32-edge loop has
// zero predicate work. Zero z-slabs are stored up front to overlap with compute.
// b lives in the LOW grid bits so co-resident blocks mix batches.
__global__ __launch_bounds__(NTHREADS, 2) void extrusion_kernel(
    const float* __restrict__ polygons,   // [B][N][P][2]
    const float* __restrict__ attributes, // [B][4]
    const float* __restrict__ validity,   // [B][N]
    float* __restrict__ out)              // [B][V][V][V]
{
    __shared__ __align__(16) float4 sA[NP * PE];   // x0, exi, syi, ey
    __shared__ __align__(16) float2 sC[NP * PE];   // ex, vy
    __shared__ __align__(16) float  sPartial[NWARPS][VX];
    __shared__ __align__(16) float  sComb[VX];
    __shared__ unsigned sParLo[NP], sParHi[NP];    // per-poly parity bitmask
    __shared__ int sIdx[NP];
    __shared__ int sV;

    const int b   = blockIdx.x & 7;        // low bits: mix batches across SMs
    const int row = blockIdx.x >> 3;
    const int tid = threadIdx.x;
    const float py = (float)row * (1.0f / 63.0f);

    // ---- Phase 0: h + early zero stores (independent of SDF) ----
    int h = (int)floorf(attributes[b * 4 + 0] * (float)VX);
    h = max(1, min(VX, h));
    float* out_base = out + (size_t)b * VX * VX * VX + (size_t)row * VX;
    const float4 zero4 = make_float4(0.f, 0.f, 0.f, 0.f);
    for (int i = h * 16 + tid; i < VX * 16; i += NTHREADS) {
        const int z = i >> 4;
        const int q = i & 15;
        ((float4*)(out_base + (size_t)z * VX * VX))[q] = zero4;
    }

    // ---- Phase 1a: validity compaction (warp 0) ----
    if (tid < 32) {
        const bool valid = validity[b * NP + tid] >= 0.5f;
        const unsigned m = __ballot_sync(0xffffffffu, valid);
        if (valid) {
            const int pos = __popc(m & ((1u << tid) - 1u));
            sIdx[pos] = tid;
        }
        if (tid == 0) sV = __popc(m);
    }

    // ---- Phase 1b: edge precompute + per-poly parity masks ----
    // warp w (0..15), lane e handles edge e of polys {w, w+16}.
    const float2* pv = (const float2*)(polygons + (size_t)b * NP * PE * 2);
    {
        const int w = tid >> 5;
        const int e = tid & 31;
        const int e1 = (e + 1) & 31;
        #pragma unroll
        for (int k = 0; k < 2; k++) {
            const int n = w + 16 * k;
            const float2 v0 = pv[n * PE + e];
            const float2 v1 = pv[n * PE + e1];
            const float ex = v1.x - v0.x;
            const float ey = v1.y - v0.y;
            const float inv = 1.0f / (ex * ex + ey * ey + EPSF);
            const float vy  = py - v0.y;
            sA[n * PE + e] = make_float4(v0.x, ex * inv, (vy * ey) * inv, ey);
            sC[n * PE + e] = make_float2(ex, vy);
            // crossing threshold -> prefix bitmask over the 64 pixel columns
            const bool ycr = (fminf(v0.y, v1.y) <= py) && (fmaxf(v0.y, v1.y) > py);
            const float interx = v0.x + ex * (vy / (ey + EPSF));
            const float cxthr = ycr ? interx : -FLT_MAX;
            float t = fminf(fmaxf(cxthr * 63.0f, -1.0f), 65.0f);
            int idx = (int)ceilf(t);
            idx = max(0, min(64, idx));
            const unsigned long long m64 =
                (idx >= 64) ? ~0ull : ((1ull << idx) - 1ull);
            const unsigned lo = __reduce_xor_sync(0xffffffffu, (unsigned)m64);
            const unsigned hi = __reduce_xor_sync(0xffffffffu, (unsigned)(m64 >> 32));
            if (e == 0) { sParLo[n] = lo; sParHi[n] = hi; }
        }
    }
    __syncthreads();

    // ---- Phase 2: SDF + sigmoid + max, 2 pixels per lane ----
    const int lane = tid & 31;
    const int g    = tid >> 5;
    const float pxa = (float)lane        * (1.0f / 63.0f);
    const float pxb = (float)(lane + 32) * (1.0f / 63.0f);
    const int nv = sV;

    float best_a = 0.0f, best_b = 0.0f;
    #pragma unroll 1
    for (int j = g; j < nv; j += NWARPS) {   // at most 2 iterations
        const int n = sIdx[j];
        const unsigned sign_a = ((sParLo[n] >> lane) & 1u) << 31;
        const unsigned sign_b = ((sParHi[n] >> lane) & 1u) << 31;
        float min_a = FLT_MAX, min_b = FLT_MAX;
        const float4* A4 = sA + n * PE;
        const float2* C2 = sC + n * PE;
        #pragma unroll
        for (int e = 0; e < PE; e++) {
            const float4 a = A4[e];       // x0, exi, syi, ey
            const float2 c = C2[e];       // ex, vy
            const float vxa = pxa - a.x;
            const float vxb = pxb - a.x;
            const float ta = __saturatef(fmaf(vxa, a.y, a.z));
            const float tb = __saturatef(fmaf(vxb, a.y, a.z));
            const float dxa = fmaf(-ta, c.x, vxa);
            const float dxb = fmaf(-tb, c.x, vxb);
            const float dya = fmaf(-ta, a.w, c.y);
            const float dyb = fmaf(-tb, a.w, c.y);
            min_a = fminf(min_a, fmaf(dya, dya, dxa * dxa));
            min_b = fminf(min_b, fmaf(dyb, dyb, dxb * dxb));
        }
        // signed distance via bit-XOR; sigmoid(-100*sdf) = 1/(1 + 2^(144.27*sdf))
        const float sa = __uint_as_float(__float_as_uint(sqrtf(min_a)) ^ sign_a);
        const float sb = __uint_as_float(__float_as_uint(sqrtf(min_b)) ^ sign_b);
        best_a = fmaxf(best_a, rcp_approx(1.0f + ex2_approx(sa * 144.269504f)));
        best_b = fmaxf(best_b, rcp_approx(1.0f + ex2_approx(sb * 144.269504f)));
    }
    sPartial[g][lane]      = best_a;
    sPartial[g][lane + 32] = best_b;
    __syncthreads();

    // ---- Phase 3: 16-way max reduce -> combined row ----
    if (tid < VX) {
        float m = sPartial[0][tid];
        #pragma unroll
        for (int w = 1; w < NWARPS; w++) m = fmaxf(m, sPartial[w][tid]);
        sComb[tid] = m;
    }
    __syncthreads();

    // ---- Phase 4: store the z < h slabs ----
    const float4* comb4 = (const float4*)sComb;
    for (int i = tid; i < h * 16; i += NTHREADS) {
        const int z = i >> 4;
        const int q = i & 15;
        ((float4*)(out_base + (size_t)z * VX * VX))[q] = comb4[q];
    }
}

extern "C" void kernel_launch(void* const* d_in, const int* in_sizes, int n_in,
                              void* d_out, int out_size) {
    const float* polygons   = (const float*)d_in[0];
    const float* attributes = (const float*)d_in[1];
    const float* validity   = (const float*)d_in[2];
    float* out = (float*)d_out;
    (void)in_sizes; (void)n_in; (void)out_size;

    extrusion_kernel<<<NB * VX, NTHREADS>>>(polygons, attributes, validity, out);
}